// round 4
// baseline (speedup 1.0000x reference)
#include <cuda_runtime.h>
#include <math.h>

#define NQ   10
#define NL   4
#define NGATE (NL * NQ)
#define WPB  4
#define NTHR (WPB * 32)
#define PI_F 3.14159265358979f
#define FULLM 0xFFFFFFFFu

typedef unsigned long long u64t;

// ---- f32x2 packed helpers ----
__device__ __forceinline__ u64t pk(float lo, float hi) {
    u64t r; asm("mov.b64 %0, {%1, %2};" : "=l"(r) : "f"(lo), "f"(hi)); return r;
}
__device__ __forceinline__ void unpk(u64t u, float& lo, float& hi) {
    asm("mov.b64 {%0, %1}, %2;" : "=f"(lo), "=f"(hi) : "l"(u));
}
__device__ __forceinline__ u64t ffma2(u64t a, u64t b, u64t c) {
    u64t r; asm("fma.rn.f32x2 %0, %1, %2, %3;" : "=l"(r) : "l"(a), "l"(b), "l"(c)); return r;
}
__device__ __forceinline__ u64t fmul2(u64t a, u64t b) {
    u64t r; asm("mul.rn.f32x2 %0, %1, %2;" : "=l"(r) : "l"(a), "l"(b)); return r;
}
__device__ __forceinline__ u64t fadd2(u64t a, u64t b) {
    u64t r; asm("add.rn.f32x2 %0, %1, %2;" : "=l"(r) : "l"(a), "l"(b)); return r;
}
__device__ __forceinline__ u64t neg2(u64t a) { return a ^ 0x8000000080000000ULL; }
__device__ __forceinline__ u64t fsub2(u64t a, u64t b) { return fadd2(a, neg2(b)); }

// packed complex multiply: (rre,rim) = (are,aim) * (bre,bim)
__device__ __forceinline__ void cmul2(u64t& rre, u64t& rim,
                                      u64t are, u64t aim, u64t bre, u64t bim) {
    rre = ffma2(are, bre, neg2(fmul2(aim, bim)));
    rim = ffma2(are, bim, fmul2(aim, bre));
}

struct G4 { float2 w00, w01, w10, w11; };

// Fused gate: W = RZ(w2)*RY(w1)*RX(w0)*RY(clip(x))
__device__ __forceinline__ G4 fuse_gate(const float* __restrict__ wq, float xv) {
    float s0, c0, s1, c1, s2, c2;
    sincosf(0.5f * wq[0], &s0, &c0);
    sincosf(0.5f * wq[1], &s1, &c1);
    sincosf(0.5f * wq[2], &s2, &c2);
    float2 M00 = make_float2( c1*c0,  s1*s0);
    float2 M01 = make_float2(-s1*c0, -c1*s0);
    float2 M10 = make_float2( s1*c0, -c1*s0);
    float2 M11 = make_float2( c1*c0, -s1*s0);
    float2 U00 = make_float2(c2*M00.x + s2*M00.y, c2*M00.y - s2*M00.x);
    float2 U01 = make_float2(c2*M01.x + s2*M01.y, c2*M01.y - s2*M01.x);
    float2 U10 = make_float2(c2*M10.x - s2*M10.y, c2*M10.y + s2*M10.x);
    float2 U11 = make_float2(c2*M11.x - s2*M11.y, c2*M11.y + s2*M11.x);
    xv = fminf(fmaxf(xv, -PI_F), PI_F);
    float sx, cx;
    sincosf(0.5f * xv, &sx, &cx);
    G4 g;
    g.w00 = make_float2( U00.x*cx + U01.x*sx,  U00.y*cx + U01.y*sx);
    g.w01 = make_float2(-U00.x*sx + U01.x*cx, -U00.y*sx + U01.y*cx);
    g.w10 = make_float2( U10.x*cx + U11.x*sx,  U10.y*cx + U11.y*sx);
    g.w11 = make_float2(-U10.x*sx + U11.x*cx, -U10.y*sx + U11.y*cx);
    return g;
}

__global__ __launch_bounds__(NTHR) void qsim_bpack_kernel(
    const float* __restrict__ xin,   // [B, NQ]
    const float* __restrict__ wts,   // [NL, NQ, 3]
    float* __restrict__ out,         // [B, NQ]
    int B)
{
    // Per-gate packed weights (element A in lo, element B in hi):
    //  [0..3]  w00.x w01.x w10.x w11.x
    //  [4..7]  w00.y w01.y w10.y w11.y
    //  [8..11] -w00.y -w01.y -w10.y -w11.y
    __shared__ u64t Wt[WPB][NGATE][12];

    const int warp = threadIdx.x >> 5;
    const int lane = threadIdx.x & 31;
    const int pbid = blockIdx.x * WPB + warp;   // batch-pair id
    const int bA = 2 * pbid, bB = bA + 1;
    if (bA >= B) return;

    // ---- Prologue: fused gates for both elements, packed
    for (int g = lane; g < NGATE; g += 32) {
        const int q = g % NQ;
        G4 a = fuse_gate(wts + g * 3, xin[bA * NQ + q]);
        G4 c = fuse_gate(wts + g * 3, xin[bB * NQ + q]);
        u64t* T = Wt[warp][g];
        T[0]  = pk(a.w00.x, c.w00.x); T[1]  = pk(a.w01.x, c.w01.x);
        T[2]  = pk(a.w10.x, c.w10.x); T[3]  = pk(a.w11.x, c.w11.x);
        T[4]  = pk(a.w00.y, c.w00.y); T[5]  = pk(a.w01.y, c.w01.y);
        T[6]  = pk(a.w10.y, c.w10.y); T[7]  = pk(a.w11.y, c.w11.y);
        T[8]  = pk(-a.w00.y, -c.w00.y); T[9]  = pk(-a.w01.y, -c.w01.y);
        T[10] = pk(-a.w10.y, -c.w10.y); T[11] = pk(-a.w11.y, -c.w11.y);
    }
    __syncwarp();

    // State: amplitude index i = (lane<<5)|r. Flat bit k <-> qubit 9-k.
    // sre[r] = (reA(i), reB(i)); sim[r] likewise.
    u64t sre[32], sim[32];

    // ---- CNOT ring, shared across layers
    auto ring = [&]() {
        // CNOT(0,1)..(3,4): lane-bit cascade; pull from lane^(lane>>1)
        const int sl = lane ^ (lane >> 1);
        #pragma unroll
        for (int r = 0; r < 32; ++r) {
            sre[r] = __shfl_sync(FULLM, sre[r], sl);
            sim[r] = __shfl_sync(FULLM, sim[r], sl);
        }
        // CNOT(4,5): control = lane bit 0, target = flat bit 4
        const bool cc = lane & 1;
        #pragma unroll
        for (int r = 0; r < 16; ++r) {
            u64t a = sre[r], b2 = sre[r + 16];
            sre[r] = cc ? b2 : a; sre[r + 16] = cc ? a : b2;
            u64t c = sim[r], d = sim[r + 16];
            sim[r] = cc ? d : c; sim[r + 16] = cc ? c : d;
        }
        // CNOT(5,6)..(8,9): static register permutation (free renaming)
        {
            u64t tr[32], ti[32];
            #pragma unroll
            for (int r = 0; r < 32; ++r) { tr[r] = sre[r ^ (r >> 1)]; ti[r] = sim[r ^ (r >> 1)]; }
            #pragma unroll
            for (int r = 0; r < 32; ++r) { sre[r] = tr[r]; sim[r] = ti[r]; }
        }
        // CNOT(9,0): control = flat bit 0 (odd r), target = lane bit 4
        #pragma unroll
        for (int r = 1; r < 32; r += 2) {
            sre[r] = __shfl_xor_sync(FULLM, sre[r], 16);
            sim[r] = __shfl_xor_sync(FULLM, sim[r], 16);
        }
    };

    // ---- Layer 1: product state  |psi> = (X) W_q |0>, column v_q = (w00, w10)
    {
        // register part over flat bits 0..4 (qubits 9..5), Kronecker doubling
        sre[0] = Wt[warp][9][0]; sim[0] = Wt[warp][9][4];   // v9[0] = w00
        sre[1] = Wt[warp][9][2]; sim[1] = Wt[warp][9][6];   // v9[1] = w10
        #pragma unroll
        for (int bit = 1; bit < 5; ++bit) {
            const int q = 9 - bit;
            const int size = 1 << bit;
            const u64t v0r = Wt[warp][q][0], v0i = Wt[warp][q][4];
            const u64t v1r = Wt[warp][q][2], v1i = Wt[warp][q][6];
            #pragma unroll
            for (int r = 0; r < 16; ++r) {
                if (r >= size) break;
                cmul2(sre[r + size], sim[r + size], sre[r], sim[r], v1r, v1i);
                u64t tr, ti;
                cmul2(tr, ti, sre[r], sim[r], v0r, v0i);
                sre[r] = tr; sim[r] = ti;
            }
        }
        // lane factor over qubits 0..4 (lane bits 4..0)
        u64t Lre, Lim;
        {
            const int bit = (lane >> 4) & 1;
            Lre = Wt[warp][0][bit ? 2 : 0]; Lim = Wt[warp][0][bit ? 6 : 4];
        }
        #pragma unroll
        for (int q = 1; q < 5; ++q) {
            const int bit = (lane >> (4 - q)) & 1;
            const u64t vr = Wt[warp][q][bit ? 2 : 0], vi = Wt[warp][q][bit ? 6 : 4];
            u64t tr, ti;
            cmul2(tr, ti, Lre, Lim, vr, vi);
            Lre = tr; Lim = ti;
        }
        #pragma unroll
        for (int r = 0; r < 32; ++r) {
            u64t tr, ti;
            cmul2(tr, ti, sre[r], sim[r], Lre, Lim);
            sre[r] = tr; sim[r] = ti;
        }
        ring();
    }

    // ---- Layers 2..4: full gate passes
    for (int l = 1; l < NL; ++l) {
        const int base = l * NQ;

        // register gates: qubits 9..5 on flat bits 0..4
        #pragma unroll
        for (int m = 0; m < 5; ++m) {
            const int q = 9 - m;
            const u64t* T = Wt[warp][base + q];
            const u64t x00 = T[0], x01 = T[1], x10 = T[2], x11 = T[3];
            const u64t y00 = T[4], y01 = T[5], y10 = T[6], y11 = T[7];
            const u64t n00 = T[8], n01 = T[9], n10 = T[10], n11 = T[11];
            #pragma unroll
            for (int r0 = 0; r0 < 32; ++r0) {
                if (r0 & (1 << m)) continue;
                const int r1 = r0 | (1 << m);
                const u64t a0r = sre[r0], a0i = sim[r0];
                const u64t a1r = sre[r1], a1i = sim[r1];
                sre[r0] = ffma2(x00, a0r, ffma2(n00, a0i, ffma2(x01, a1r, fmul2(n01, a1i))));
                sim[r0] = ffma2(x00, a0i, ffma2(y00, a0r, ffma2(x01, a1i, fmul2(y01, a1r))));
                sre[r1] = ffma2(x10, a0r, ffma2(n10, a0i, ffma2(x11, a1r, fmul2(n11, a1i))));
                sim[r1] = ffma2(x10, a0i, ffma2(y10, a0r, ffma2(x11, a1i, fmul2(y11, a1r))));
            }
        }

        // lane gates: qubits 0..4 on lane bits 4..0 (u64 shuffle exchange)
        #pragma unroll
        for (int q = 0; q < 5; ++q) {
            const int lb = 4 - q;
            const u64t* T = Wt[warp][base + q];
            const bool row = (lane >> lb) & 1;
            const int oi = row ? 3 : 0, pi = row ? 2 : 1;
            const u64t ownx = T[oi],      othx = T[pi];
            const u64t owny = T[4 + oi],  othy = T[4 + pi];
            const u64t ownny = T[8 + oi], othny = T[8 + pi];
            #pragma unroll
            for (int r = 0; r < 32; ++r) {
                const u64t pre = __shfl_xor_sync(FULLM, sre[r], 1 << lb);
                const u64t pim = __shfl_xor_sync(FULLM, sim[r], 1 << lb);
                const u64t are = sre[r], aim = sim[r];
                sre[r] = ffma2(ownx, are, ffma2(ownny, aim, ffma2(othx, pre, fmul2(othny, pim))));
                sim[r] = ffma2(ownx, aim, ffma2(owny, are, ffma2(othx, pim, fmul2(othy, pre))));
            }
        }

        ring();
    }

    // ---- Expectation values (packed over both elements)
    u64t v0[32];
    #pragma unroll
    for (int r = 0; r < 32; ++r)
        v0[r] = ffma2(sim[r], sim[r], fmul2(sre[r], sre[r]));

    u64t zr[5];
    u64t v1[16], v2[8], v3[4], v4[2];
    {
        u64t d = 0ull;
        #pragma unroll
        for (int k = 0; k < 16; ++k) { d = fadd2(d, fsub2(v0[2*k], v0[2*k+1])); v1[k] = fadd2(v0[2*k], v0[2*k+1]); }
        zr[0] = d; d = 0ull;
        #pragma unroll
        for (int k = 0; k < 8; ++k)  { d = fadd2(d, fsub2(v1[2*k], v1[2*k+1])); v2[k] = fadd2(v1[2*k], v1[2*k+1]); }
        zr[1] = d; d = 0ull;
        #pragma unroll
        for (int k = 0; k < 4; ++k)  { d = fadd2(d, fsub2(v2[2*k], v2[2*k+1])); v3[k] = fadd2(v2[2*k], v2[2*k+1]); }
        zr[2] = d; d = 0ull;
        #pragma unroll
        for (int k = 0; k < 2; ++k)  { d = fadd2(d, fsub2(v3[2*k], v3[2*k+1])); v4[k] = fadd2(v3[2*k], v3[2*k+1]); }
        zr[3] = d;
        zr[4] = fsub2(v4[0], v4[1]);
    }
    const u64t s_tot = fadd2(v4[0], v4[1]);

    u64t z[NQ];
    #pragma unroll
    for (int q = 0; q < 5; ++q)
        z[q] = ((lane >> (4 - q)) & 1) ? neg2(s_tot) : s_tot;
    #pragma unroll
    for (int q = 5; q < NQ; ++q)
        z[q] = zr[9 - q];

    #pragma unroll
    for (int q = 0; q < NQ; ++q) {
        u64t v = z[q];
        #pragma unroll
        for (int off = 16; off > 0; off >>= 1)
            v = fadd2(v, __shfl_xor_sync(FULLM, v, off));
        z[q] = v;
    }
    if (lane == 0) {
        #pragma unroll
        for (int q = 0; q < NQ; ++q) {
            float za, zb;
            unpk(z[q], za, zb);
            out[bA * NQ + q] = za;
            out[bB * NQ + q] = zb;
        }
    }
}

extern "C" void kernel_launch(void* const* d_in, const int* in_sizes, int n_in,
                              void* d_out, int out_size) {
    const float* xin = (const float*)d_in[0];   // [B, 10] f32
    const float* wts = (const float*)d_in[1];   // [4, 10, 3] f32
    float* out = (float*)d_out;                 // [B, 10] f32
    const int batch = in_sizes[0] / NQ;         // 4096 (even)
    const int pairs = batch / 2;
    const int blocks = (pairs + WPB - 1) / WPB;
    qsim_bpack_kernel<<<blocks, NTHR>>>(xin, wts, out, batch);
}